// round 15
// baseline (speedup 1.0000x reference)
#include <cuda_runtime.h>
#include <cuda_bf16.h>
#include <cstdint>
#include <math.h>

#define NB 2
#define NQ 100
#define NC 256
#define NHW 64
#define NP 6
#define WSZ 7
#define WS2 49
#define NHD 8
#define HDD 32
#define NWIN 600            // Q*NP
#define NROWS 58800         // NB*NWIN*WS2
#define MPAD 58880          // 460*128 (GEMM M padding)
#define KD 256
#define NOUT3 768
#define OB_PER_B 7526400    // NHD*WS2*NWIN*HDD

// -------- scratch (static device globals; no runtime alloc allowed) --------
__device__ float g_xt[NB * NHW * NHW * NC];            // x transposed to (b,y,x,c)
__device__ __nv_bfloat16 g_ahi[(size_t)MPAD * KD];     // sampled features hi (bf16)
__device__ __nv_bfloat16 g_alo[(size_t)MPAD * KD];     // sampled features lo (bf16)
__device__ uint4 g_bfrag[96 * 16 * 32];                // w_qkv in MMA-fragment order
__device__ uint2 g_qhl[(size_t)MPAD * NOUT3 / 2];      // qkv: per col-pair {hi2, lo2}
__device__ float g_o[(size_t)NB * OB_PER_B];           // attention out (scrambled-flat layout)
__device__ float g_ypre[NB * NWIN * NC];               // conv-reduced
__device__ float g_wpT[NC * NC];                       // w_proj transposed

// ======================= mma.sync / cp.async helpers (baseline ISA) =======================
__device__ __forceinline__ uint32_t smem_u32(const void* p) {
    uint32_t a;
    asm("{ .reg .u64 t; cvta.to.shared.u64 t, %1; cvt.u32.u64 %0, t; }" : "=r"(a) : "l"(p));
    return a;
}
__device__ __forceinline__ void ldsm_x4(uint32_t* r, uint32_t addr) {
    asm volatile("ldmatrix.sync.aligned.m8n8.x4.shared.b16 {%0,%1,%2,%3}, [%4];"
                 : "=r"(r[0]), "=r"(r[1]), "=r"(r[2]), "=r"(r[3]) : "r"(addr));
}
__device__ __forceinline__ void mma16816(float* c, const uint32_t* a, const uint32_t* b) {
    asm volatile("mma.sync.aligned.m16n8k16.row.col.f32.bf16.bf16.f32 "
                 "{%0,%1,%2,%3}, {%4,%5,%6,%7}, {%8,%9}, {%0,%1,%2,%3};"
                 : "+f"(c[0]), "+f"(c[1]), "+f"(c[2]), "+f"(c[3])
                 : "r"(a[0]), "r"(a[1]), "r"(a[2]), "r"(a[3]), "r"(b[0]), "r"(b[1]));
}
__device__ __forceinline__ void cp_async16(uint32_t saddr, const void* gptr) {
    asm volatile("cp.async.cg.shared.global [%0], [%1], 16;" :: "r"(saddr), "l"(gptr));
}
#define CP_COMMIT() asm volatile("cp.async.commit_group;" ::: "memory")
#define CP_WAIT1() asm volatile("cp.async.wait_group 1;" ::: "memory")
#define CP_WAIT0() asm volatile("cp.async.wait_group 0;" ::: "memory")

__device__ __forceinline__ uint32_t pack_bf2_hi(float a, float b) {
    __nv_bfloat162 t; t.x = __float2bfloat16(a); t.y = __float2bfloat16(b);
    return *(uint32_t*)&t;
}
__device__ __forceinline__ uint32_t pack_bf2_lo(float a, float b) {
    float ra = a - __bfloat162float(__float2bfloat16(a));
    float rb = b - __bfloat162float(__float2bfloat16(b));
    __nv_bfloat162 t; t.x = __float2bfloat16(ra); t.y = __float2bfloat16(rb);
    return *(uint32_t*)&t;
}

// -------- K0: x (B,C,H,W) -> xt (B,H,W,C), tiled transpose --------
__global__ void k_transpose_x(const float* __restrict__ x) {
    __shared__ float tile[32][33];
    int b = blockIdx.z;
    int c0 = blockIdx.y * 32, p0 = blockIdx.x * 32;
    #pragma unroll
    for (int i = threadIdx.y; i < 32; i += 8)
        tile[i][threadIdx.x] = x[((size_t)(b * NC + c0 + i) << 12) + p0 + threadIdx.x];
    __syncthreads();
    #pragma unroll
    for (int i = threadIdx.y; i < 32; i += 8)
        g_xt[(((size_t)b << 12) + p0 + i) * NC + c0 + threadIdx.x] = tile[threadIdx.x][i];
}

// -------- K1: poly eval + bilinear sample -> Ahi/Alo[b,n,s,c] (bf16 split) --------
__global__ void k_sample(const float* __restrict__ polys) {
    int j = blockIdx.x;                                // 0..58799 = ((b*600+n)*49+s)
    int t = threadIdx.x;                               // 0..63, 4 channels each
    int b = j / (NWIN * WS2);
    int r = j - b * (NWIN * WS2);
    int n = r / WS2;
    int s = r - n * WS2;
    int q = n / NP;
    int nid = n - q * NP;
    int m = nid * WS2 + s;
    int w = m / NP;
    int p = m - w * NP;

    const float* pc = polys + ((size_t)(b * NQ + q) * 2) * NP;
    float a = (float)p * 0.2f;
    float py = pc[0];
    #pragma unroll
    for (int i = 1; i < NP; i++) py = py * a + pc[i];
    float px = pc[NP];
    #pragma unroll
    for (int i = 1; i < NP; i++) px = px * a + pc[NP + i];
    py = 2.f * py - 1.f;
    px = 2.f * px - 1.f;

    int wy = w / WSZ, wx = w - wy * WSZ;
    float dy = (-4.0f + (float)wy * (7.0f / 6.0f)) * (2.0f / 64.0f);
    float dx = (-4.0f + (float)wx * (7.0f / 6.0f)) * (2.0f / 64.0f);
    float gy = py + dy, gx = px + dx;

    float fx = (gy + 1.f) * 0.5f * 63.f;
    float fy = (gx + 1.f) * 0.5f * 63.f;
    float x0f = floorf(fx), y0f = floorf(fy);
    float wx1 = fx - x0f, wy1 = fy - y0f;

    float vx0 = (x0f >= 0.f && x0f <= 63.f) ? 1.f : 0.f;
    float vx1 = (x0f + 1.f >= 0.f && x0f + 1.f <= 63.f) ? 1.f : 0.f;
    float vy0 = (y0f >= 0.f && y0f <= 63.f) ? 1.f : 0.f;
    float vy1 = (y0f + 1.f >= 0.f && y0f + 1.f <= 63.f) ? 1.f : 0.f;
    int xi0 = min(max((int)x0f, 0), 63);
    int xi1 = min(max((int)x0f + 1, 0), 63);
    int yi0 = min(max((int)y0f, 0), 63);
    int yi1 = min(max((int)y0f + 1, 0), 63);

    float w00 = (1.f - wy1) * (1.f - wx1) * vy0 * vx0;
    float w01 = (1.f - wy1) * wx1 * vy0 * vx1;
    float w10 = wy1 * (1.f - wx1) * vy1 * vx0;
    float w11 = wy1 * wx1 * vy1 * vx1;

    const float4* xt4 = (const float4*)g_xt;
    size_t pbase = (size_t)b * 4096;
    const float4* p00 = xt4 + (pbase + yi0 * 64 + xi0) * 64;
    const float4* p01 = xt4 + (pbase + yi0 * 64 + xi1) * 64;
    const float4* p10 = xt4 + (pbase + yi1 * 64 + xi0) * 64;
    const float4* p11 = xt4 + (pbase + yi1 * 64 + xi1) * 64;
    float4 v00 = p00[t], v01 = p01[t], v10 = p10[t], v11 = p11[t];
    float4 o;
    o.x = w00 * v00.x + w01 * v01.x + w10 * v10.x + w11 * v11.x;
    o.y = w00 * v00.y + w01 * v01.y + w10 * v10.y + w11 * v11.y;
    o.z = w00 * v00.z + w01 * v01.z + w10 * v10.z + w11 * v11.z;
    o.w = w00 * v00.w + w01 * v01.w + w10 * v10.w + w11 * v11.w;

    uint2 hv, lv;
    hv.x = pack_bf2_hi(o.x, o.y); hv.y = pack_bf2_hi(o.z, o.w);
    lv.x = pack_bf2_lo(o.x, o.y); lv.y = pack_bf2_lo(o.z, o.w);
    size_t base2 = (size_t)j * 64 + t;                 // uint2 units
    ((uint2*)g_ahi)[base2] = hv;
    ((uint2*)g_alo)[base2] = lv;
}

// -------- K1b: w_qkv -> per-lane MMA B-fragments (hi/lo packed in one uint4) --------
__global__ void k_wfrag(const float* __restrict__ wq) {
    int i = blockIdx.x * 256 + threadIdx.x;            // < 49152
    int lane = i & 31;
    int kt = (i >> 5) & 15;
    int nt = i >> 9;
    int n = nt * 8 + (lane >> 2);
    int kb = kt * 16 + (lane & 3) * 2;
    const float* row = wq + (size_t)n * KD;
    float v00 = row[kb],     v01 = row[kb + 1];
    float v10 = row[kb + 8], v11 = row[kb + 9];
    uint4 bf;
    bf.x = pack_bf2_hi(v00, v01);
    bf.y = pack_bf2_hi(v10, v11);
    bf.z = pack_bf2_lo(v00, v01);
    bf.w = pack_bf2_lo(v10, v11);
    g_bfrag[i] = bf;
}

// -------- K2: HMMA GEMM, CTA tile 128x64, 3 CTAs/SM (24 warps) --------
// 8 warps in 4m x 2n grid, warp tile 32x32, K chunk 64 (4 iters).
// 3 bf16 terms: Ah*Bh + Ah*Bl + Al*Bh. Dep spacing 4 via j-pair interleave.
#define SROWB 144                   // smem row stride bytes (64 bf16 data + 16B pad)
#define ARR2_B (128 * SROWB)        // 18432 B per array
#define STAGE2_B (2 * ARR2_B)       // 36864 B per stage (A hi + A lo)
#define GSM_TOTAL (2 * STAGE2_B)    // 73728 B

__global__ void __launch_bounds__(256, 3) k_gemm_mma(const float* __restrict__ bq) {
    extern __shared__ __align__(16) char dsm[];
    int tid = threadIdx.x;
    int wid = tid >> 5, lid = tid & 31;
    int wm = wid >> 1, wn = wid & 1;                   // 4m x 2n warp grid
    int bm = blockIdx.x * 128, bn = blockIdx.y * 64;

    float acc[2][4][4];
    #pragma unroll
    for (int t = 0; t < 2; t++)
        #pragma unroll
        for (int j = 0; j < 4; j++)
            #pragma unroll
            for (int e = 0; e < 4; e++) acc[t][j][e] = 0.f;

    uint32_t sbase = smem_u32(dsm);

    const char* GAh = (const char*)g_ahi;
    const char* GAl = (const char*)g_alo;
    const uint4* BF = (const uint4*)g_bfrag;
    int wb = ((bn + wn * 32) >> 3) * 512 + lid;        // warp covers 32 N-cols = 4 n-tiles

    int arow = lid & 15;
    int acolb = (lid >> 4) * 16;
    uint32_t aA0 = (uint32_t)((wm * 32 + arow) * SROWB) + acolb;

    auto load_stage = [&](int kc, int st) {
        uint32_t sb = sbase + st * STAGE2_B;
        #pragma unroll
        for (int i = tid; i < 1024; i += 256) {
            int row = i >> 3, u = i & 7;
            uint32_t so = (uint32_t)(row * SROWB) + u * 16;
            size_t ga = (size_t)(bm + row) * 512 + kc * 128 + u * 16;
            cp_async16(sb + so,          GAh + ga);
            cp_async16(sb + ARR2_B + so, GAl + ga);
        }
    };

    load_stage(0, 0);
    CP_COMMIT();

    for (int kc = 0; kc < 4; kc++) {
        int st = kc & 1;
        if (kc < 3) {
            load_stage(kc + 1, st ^ 1);
            CP_COMMIT();
            CP_WAIT1();
        } else {
            CP_WAIT0();
        }
        __syncthreads();

        uint32_t uAh = sbase + st * STAGE2_B;
        uint32_t uAl = uAh + ARR2_B;
        #pragma unroll
        for (int ks = 0; ks < 4; ks++) {
            int ktoff = (kc * 4 + ks) * 32;
            uint32_t ah[2][4], al[2][4];
            ldsm_x4(ah[0], uAh + aA0 + ks * 32);
            ldsm_x4(ah[1], uAh + aA0 + 16 * SROWB + ks * 32);
            ldsm_x4(al[0], uAl + aA0 + ks * 32);
            ldsm_x4(al[1], uAl + aA0 + 16 * SROWB + ks * 32);
            uint4 b0 = BF[wb + 0 * 512 + ktoff];
            uint4 b1 = BF[wb + 1 * 512 + ktoff];
            #pragma unroll
            for (int jp = 0; jp < 2; jp++) {
                uint4 n0, n1;
                if (jp < 1) {
                    n0 = BF[wb + 2 * 512 + ktoff];
                    n1 = BF[wb + 3 * 512 + ktoff];
                }
                int ja = jp * 2, jb = ja + 1;
                const uint32_t* p0 = (const uint32_t*)&b0;
                const uint32_t* p1 = (const uint32_t*)&b1;
                mma16816(acc[0][ja], ah[0], p0);
                mma16816(acc[0][jb], ah[0], p1);
                mma16816(acc[1][ja], ah[1], p0);
                mma16816(acc[1][jb], ah[1], p1);
                mma16816(acc[0][ja], ah[0], p0 + 2);
                mma16816(acc[0][jb], ah[0], p1 + 2);
                mma16816(acc[1][ja], ah[1], p0 + 2);
                mma16816(acc[1][jb], ah[1], p1 + 2);
                mma16816(acc[0][ja], al[0], p0);
                mma16816(acc[0][jb], al[0], p1);
                mma16816(acc[1][ja], al[1], p0);
                mma16816(acc[1][jb], al[1], p1);
                b0 = n0; b1 = n1;
            }
        }
        __syncthreads();
    }

    // epilogue: c-frag + bias -> interleaved uint2 {hi2, lo2} per col-pair
    int crow0 = bm + wm * 32 + (lid >> 2);
    int ccol0 = bn + wn * 32 + (lid & 3) * 2;
    #pragma unroll
    for (int t = 0; t < 2; t++) {
        #pragma unroll
        for (int j = 0; j < 4; j++) {
            int col = ccol0 + j * 8;
            float b0 = __ldg(&bq[col]);
            float b1 = __ldg(&bq[col + 1]);
            int row = crow0 + t * 16;
            float v00 = acc[t][j][0] + b0, v01 = acc[t][j][1] + b1;
            float v10 = acc[t][j][2] + b0, v11 = acc[t][j][3] + b1;
            uint2 s0, s1;
            s0.x = pack_bf2_hi(v00, v01); s0.y = pack_bf2_lo(v00, v01);
            s1.x = pack_bf2_hi(v10, v11); s1.y = pack_bf2_lo(v10, v11);
            g_qhl[((size_t)row * NOUT3 + col) >> 1] = s0;
            g_qhl[((size_t)(row + 8) * NOUT3 + col) >> 1] = s1;
        }
    }
}

// -------- K3: HMMA windowed attention, one (b,h,n) per block, 128 threads --------
// Pad rows/cols of q/k/P left as garbage: they only propagate to S rows>=49,
// S cols>=52 (masked in softmax) and O rows>=49 (never stored). vT pad cols are
// zero-filled in the fill loop (needed: P=0 x V=NaN would poison O).
#define ATT_QH 0            // 64 x 80B  (later PH: 64 x 144B)
#define ATT_QL 5120
#define ATT_KH 10240        // (later PL)
#define ATT_KL 15360
#define ATT_VTH 20480       // 32 x 144B
#define ATT_VTL 25088
#define ATT_S 29696         // 64 x 68 floats = 17408 (reused as O: 64 x 36 floats)
#define ATT_PH 0
#define ATT_PL 10240
#define ATT_SM 47104
#define SSTR 68

__global__ void __launch_bounds__(128) k_attn_mma(const float* __restrict__ pos_bias) {
    extern __shared__ __align__(16) char sma[];
    int tid = threadIdx.x;
    int wid = tid >> 5, lid = tid & 31;
    int blk = blockIdx.x;
    int b = blk / (NHD * NWIN);
    int r = blk - b * NHD * NWIN;
    int h = r / NWIN;
    int n = r - h * NWIN;
    uint32_t sb = smem_u32(sma);

    // 1. fill q/k (rows<49) and transposed v (cols>=49 zeroed inline)
    const uint4* GQ = (const uint4*)g_qhl;             // 1 uint4 = 4 cols {hi2,lo2}x2
    int grow0 = (b * NWIN + n) * WS2;
    for (int idx = tid; idx < 392; idx += 128) {       // q+k: 49 rows x 8 colgroups
        int row = idx >> 3, cg = idx & 7;
        size_t base = (size_t)(grow0 + row) * 192 + h * 8 + cg;
        uint4 vq = GQ[base];
        uint4 vk = GQ[base + 64];
        uint2 qh; qh.x = vq.x; qh.y = vq.z;
        uint2 ql; ql.x = vq.y; ql.y = vq.w;
        uint2 kh; kh.x = vk.x; kh.y = vk.z;
        uint2 kl; kl.x = vk.y; kl.y = vk.w;
        *(uint2*)(sma + ATT_QH + row * 80 + cg * 8) = qh;
        *(uint2*)(sma + ATT_QL + row * 80 + cg * 8) = ql;
        *(uint2*)(sma + ATT_KH + row * 80 + cg * 8) = kh;
        *(uint2*)(sma + ATT_KL + row * 80 + cg * 8) = kl;
    }
    for (int idx = tid; idx < 1024; idx += 128) {      // vT: [d=32][c=64]
        int c = idx >> 4, u = idx & 15;                // u = d-pair
        uint2 w = make_uint2(0u, 0u);
        if (c < WS2)
            w = ((const uint2*)g_qhl)[(size_t)(grow0 + c) * 384 + 256 + h * 16 + u];
        __nv_bfloat162 vh2 = *(__nv_bfloat162*)&w.x;
        __nv_bfloat162 vl2 = *(__nv_bfloat162*)&w.y;
        __nv_bfloat16* th = (__nv_bfloat16*)(sma + ATT_VTH);
        __nv_bfloat16* tl = (__nv_bfloat16*)(sma + ATT_VTL);
        th[(2 * u) * 72 + c] = vh2.x; th[(2 * u + 1) * 72 + c] = vh2.y;
        tl[(2 * u) * 72 + c] = vl2.x; tl[(2 * u + 1) * 72 + c] = vl2.y;
    }
    __syncthreads();

    // 2. S = q k^T via HMMA (3-term hi/lo)
    {
        float accs[8][4];
        #pragma unroll
        for (int j = 0; j < 8; j++)
            #pragma unroll
            for (int e = 0; e < 4; e++) accs[j][e] = 0.f;
        int arow = lid & 15, acolb = (lid >> 4) * 16;
        int brow = ((lid >> 4) & 1) * 8 + (lid & 7);
        int bcolb = ((lid >> 3) & 1) * 16;
        uint32_t aQh = sb + ATT_QH + (wid * 16 + arow) * 80 + acolb;
        uint32_t aQl = sb + ATT_QL + (wid * 16 + arow) * 80 + acolb;
        uint32_t aKh = sb + ATT_KH + brow * 80 + bcolb;
        uint32_t aKl = sb + ATT_KL + brow * 80 + bcolb;
        #pragma unroll
        for (int ks = 0; ks < 2; ks++) {
            uint32_t ah[4], al[4];
            ldsm_x4(ah, aQh + ks * 32);
            ldsm_x4(al, aQl + ks * 32);
            #pragma unroll
            for (int g = 0; g < 4; g++) {
                uint32_t bh[4], bl[4];
                ldsm_x4(bh, aKh + g * 16 * 80 + ks * 32);
                ldsm_x4(bl, aKl + g * 16 * 80 + ks * 32);
                mma16816(accs[g * 2],     ah, bh);
                mma16816(accs[g * 2 + 1], ah, bh + 2);
                mma16816(accs[g * 2],     ah, bl);
                mma16816(accs[g * 2 + 1], ah, bl + 2);
                mma16816(accs[g * 2],     al, bh);
                mma16816(accs[g * 2 + 1], al, bh + 2);
            }
        }
        float* S = (float*)(sma + ATT_S);
        int srow = wid * 16 + (lid >> 2), scol = (lid & 3) * 2;
        #pragma unroll
        for (int j = 0; j < 8; j++) {
            *(float2*)&S[srow * SSTR + j * 8 + scol]       = make_float2(accs[j][0], accs[j][1]);
            *(float2*)&S[(srow + 8) * SSTR + j * 8 + scol] = make_float2(accs[j][2], accs[j][3]);
        }
    }
    __syncthreads();

    // 3. vectorized fp32 softmax per row (<49); write full 144B P rows (tails = 0)
    if (tid < WS2) {
        const float scale = 0.17677669529663687f;
        float pb = pos_bias[tid];
        const float4* S4 = (const float4*)(sma + ATT_S) + tid * (SSTR / 4);
        float4 rv[13];
        #pragma unroll
        for (int i = 0; i < 13; i++) rv[i] = S4[i];
        #pragma unroll
        for (int i = 0; i < 13; i++) {
            rv[i].x = rv[i].x * scale + pb; rv[i].y = rv[i].y * scale + pb;
            rv[i].z = rv[i].z * scale + pb; rv[i].w = rv[i].w * scale + pb;
        }
        float mx = rv[12].x;
        #pragma unroll
        for (int i = 0; i < 12; i++)
            mx = fmaxf(mx, fmaxf(fmaxf(rv[i].x, rv[i].y), fmaxf(rv[i].z, rv[i].w)));
        float sum = 0.f;
        #pragma unroll
        for (int i = 0; i < 12; i++) {
            rv[i].x = __expf(rv[i].x - mx); rv[i].y = __expf(rv[i].y - mx);
            rv[i].z = __expf(rv[i].z - mx); rv[i].w = __expf(rv[i].w - mx);
            sum += rv[i].x + rv[i].y + rv[i].z + rv[i].w;
        }
        rv[12].x = __expf(rv[12].x - mx);
        rv[12].y = 0.f; rv[12].z = 0.f; rv[12].w = 0.f;
        sum += rv[12].x;
        float inv = 1.f / sum;
        uint32_t* PH32 = (uint32_t*)(sma + ATT_PH) + tid * 36;
        uint32_t* PL32 = (uint32_t*)(sma + ATT_PL) + tid * 36;
        #pragma unroll
        for (int cp = 0; cp < 26; cp++) {
            float a  = ((cp & 1) ? rv[cp >> 1].z : rv[cp >> 1].x) * inv;
            float b2 = ((cp & 1) ? rv[cp >> 1].w : rv[cp >> 1].y) * inv;
            PH32[cp] = pack_bf2_hi(a, b2);
            PL32[cp] = pack_bf2_lo(a, b2);
        }
        #pragma unroll
        for (int cp = 26; cp < 36; cp++) { PH32[cp] = 0u; PL32[cp] = 0u; }
    }
    __syncthreads();

    // 4. O = P V via HMMA (3-term)
    {
        float acco[4][4];
        #pragma unroll
        for (int j = 0; j < 4; j++)
            #pragma unroll
            for (int e = 0; e < 4; e++) acco[j][e] = 0.f;
        int arow = lid & 15, acolb = (lid >> 4) * 16;
        int brow = ((lid >> 4) & 1) * 8 + (lid & 7);
        int bcolb = ((lid >> 3) & 1) * 16;
        uint32_t aPh = sb + ATT_PH + (wid * 16 + arow) * 144 + acolb;
        uint32_t aPl = sb + ATT_PL + (wid * 16 + arow) * 144 + acolb;
        uint32_t aVh = sb + ATT_VTH + brow * 144 + bcolb;
        uint32_t aVl = sb + ATT_VTL + brow * 144 + bcolb;
        #pragma unroll
        for (int ks = 0; ks < 4; ks++) {
            uint32_t ph[4], pl[4];
            ldsm_x4(ph, aPh + ks * 32);
            ldsm_x4(pl, aPl + ks * 32);
            #pragma unroll
            for (int g = 0; g < 2; g++) {
                uint32_t vh[4], vl[4];
                ldsm_x4(vh, aVh + g * 16 * 144 + ks * 32);
                ldsm_x4(vl, aVl + g * 16 * 144 + ks * 32);
                mma16816(acco[g * 2],     ph, vh);
                mma16816(acco[g * 2 + 1], ph, vh + 2);
                mma16816(acco[g * 2],     ph, vl);
                mma16816(acco[g * 2 + 1], ph, vl + 2);
                mma16816(acco[g * 2],     pl, vh);
                mma16816(acco[g * 2 + 1], pl, vh + 2);
            }
        }
        float* O = (float*)(sma + ATT_S);
        int orow = wid * 16 + (lid >> 2), ocol = (lid & 3) * 2;
        #pragma unroll
        for (int j = 0; j < 4; j++) {
            *(float2*)&O[orow * 36 + j * 8 + ocol]       = make_float2(acco[j][0], acco[j][1]);
            *(float2*)&O[(orow + 8) * 36 + j * 8 + ocol] = make_float2(acco[j][2], acco[j][3]);
        }
    }
    __syncthreads();

    // 5. store o[p<49][d<32] to scrambled-flat g_o
    size_t obase = (size_t)b * OB_PER_B + (size_t)h * (WS2 * NWIN * HDD) + (size_t)n * HDD;
    const float* O = (const float*)(sma + ATT_S);
    for (int idx = tid; idx < WS2 * 8; idx += 128) {
        int p = idx >> 3, d4 = (idx & 7) * 4;
        float4 v = *(const float4*)&O[p * 36 + d4];
        *(float4*)&g_o[obase + (size_t)p * (NWIN * HDD) + d4] = v;
    }
}

// -------- K4: conv reduce over scrambled s2 axis (float4) --------
__global__ void k_conv(const float* __restrict__ conv_w, const float* __restrict__ conv_b) {
    __shared__ float cw[WS2];
    int tid = threadIdx.x;
    if (tid < WS2) cw[tid] = conv_w[tid];
    __syncthreads();
    int idx = blockIdx.x * 256 + tid;                  // < 76800 (c4 granularity)
    int b = idx / (NWIN * 64);
    int r = idx - b * (NWIN * 64);
    int n2 = r >> 6, c4 = r & 63;
    size_t base = (size_t)b * OB_PER_B + (size_t)n2 * (WS2 * NC) + c4 * 4;
    float cb = conv_b[0];
    float4 acc = make_float4(cb, cb, cb, cb);
    #pragma unroll 7
    for (int s2 = 0; s2 < WS2; s2++) {
        float4 v = *(const float4*)&g_o[base + (size_t)s2 * NC];
        float w = cw[s2];
        acc.x += w * v.x; acc.y += w * v.y; acc.z += w * v.z; acc.w += w * v.w;
    }
    *(float4*)&g_ypre[(size_t)idx * 4] = acc;
}

// -------- K5a: transpose w_proj --------
__global__ void k_wpt(const float* __restrict__ wp) {
    int idx = blockIdx.x * 256 + threadIdx.x;          // < 65536
    int k = idx >> 8, c = idx & 255;
    g_wpT[idx] = wp[c * NC + k];
}

// -------- K5b: y = ypre @ w_proj^T + b_proj (8 rows/block) --------
#define PR 8
__global__ void __launch_bounds__(256) k_proj(const float* __restrict__ bp, float* __restrict__ out) {
    __shared__ float rowv[PR][NC];
    int row0 = blockIdx.x * PR;
    int tid = threadIdx.x;
    for (int i = tid; i < PR * NC; i += 256)
        rowv[i >> 8][i & 255] = g_ypre[(size_t)(row0 + (i >> 8)) * NC + (i & 255)];
    __syncthreads();
    int c = tid;
    float acc[PR];
    #pragma unroll
    for (int i = 0; i < PR; i++) acc[i] = 0.f;
    #pragma unroll 4
    for (int k = 0; k < NC; k++) {
        float wv = g_wpT[k * NC + c];
        #pragma unroll
        for (int i = 0; i < PR; i++) acc[i] += rowv[i][k] * wv;
    }
    float bb = bp[c];
    #pragma unroll
    for (int i = 0; i < PR; i++)
        out[(size_t)(row0 + i) * NC + c] = acc[i] + bb;
}

extern "C" void kernel_launch(void* const* d_in, const int* in_sizes, int n_in,
                              void* d_out, int out_size) {
    const float* x        = (const float*)d_in[0];
    const float* polys    = (const float*)d_in[1];
    const float* w_qkv    = (const float*)d_in[2];
    const float* b_qkv    = (const float*)d_in[3];
    const float* w_proj   = (const float*)d_in[4];
    const float* b_proj   = (const float*)d_in[5];
    const float* conv_w   = (const float*)d_in[6];
    const float* conv_b   = (const float*)d_in[7];
    const float* pos_bias = (const float*)d_in[8];
    float* out = (float*)d_out;

    static int smem_set = 0;
    if (!smem_set) {
        cudaFuncSetAttribute(k_gemm_mma, cudaFuncAttributeMaxDynamicSharedMemorySize, GSM_TOTAL);
        cudaFuncSetAttribute(k_attn_mma, cudaFuncAttributeMaxDynamicSharedMemorySize, ATT_SM);
        smem_set = 1;
    }

    dim3 gt(128, 8, 2);
    dim3 bt(32, 8);
    k_transpose_x<<<gt, bt>>>(x);
    k_sample<<<NROWS, 64>>>(polys);
    k_wfrag<<<(96 * 16 * 32) / 256, 256>>>(w_qkv);
    dim3 g2(MPAD / 128, NOUT3 / 64);
    k_gemm_mma<<<g2, 256, GSM_TOTAL>>>(b_qkv);
    k_attn_mma<<<NB * NHD * NWIN, 128, ATT_SM>>>(pos_bias);
    k_conv<<<(NB * NWIN * 64) / 256, 256>>>(conv_w, conv_b);
    k_wpt<<<NC * NC / 256, 256>>>(w_proj);
    k_proj<<<NB * NWIN / PR, 256>>>(b_proj, out);
}

// round 16
// speedup vs baseline: 1.3499x; 1.3499x over previous
#include <cuda_runtime.h>
#include <cuda_bf16.h>
#include <cstdint>
#include <math.h>

#define NB 2
#define NQ 100
#define NC 256
#define NHW 64
#define NP 6
#define WSZ 7
#define WS2 49
#define NHD 8
#define HDD 32
#define NWIN 600            // Q*NP
#define NROWS 58800         // NB*NWIN*WS2
#define MPAD 58880          // 460*128 (GEMM M padding)
#define KD 256
#define NOUT3 768
#define OB_PER_B 7526400    // NHD*WS2*NWIN*HDD

// -------- scratch (static device globals; no runtime alloc allowed) --------
__device__ float g_xt[NB * NHW * NHW * NC];            // x transposed to (b,y,x,c)
__device__ __nv_bfloat16 g_ahi[(size_t)MPAD * KD];     // sampled features hi (bf16)
__device__ __nv_bfloat16 g_alo[(size_t)MPAD * KD];     // sampled features lo (bf16)
__device__ uint4 g_bfrag[96 * 16 * 32];                // w_qkv in MMA-fragment order
__device__ uint2 g_qhl[(size_t)MPAD * NOUT3 / 2];      // qkv: per col-pair {hi2, lo2}
__device__ float g_o[(size_t)NB * OB_PER_B];           // attention out (scrambled-flat layout)
__device__ float g_ypre[NB * NWIN * NC];               // conv-reduced
__device__ float g_wpT[NC * NC];                       // w_proj transposed

// ======================= mma.sync / cp.async helpers (baseline ISA) =======================
__device__ __forceinline__ uint32_t smem_u32(const void* p) {
    uint32_t a;
    asm("{ .reg .u64 t; cvta.to.shared.u64 t, %1; cvt.u32.u64 %0, t; }" : "=r"(a) : "l"(p));
    return a;
}
__device__ __forceinline__ void ldsm_x4(uint32_t* r, uint32_t addr) {
    asm volatile("ldmatrix.sync.aligned.m8n8.x4.shared.b16 {%0,%1,%2,%3}, [%4];"
                 : "=r"(r[0]), "=r"(r[1]), "=r"(r[2]), "=r"(r[3]) : "r"(addr));
}
__device__ __forceinline__ void mma16816(float* c, const uint32_t* a, const uint32_t* b) {
    asm volatile("mma.sync.aligned.m16n8k16.row.col.f32.bf16.bf16.f32 "
                 "{%0,%1,%2,%3}, {%4,%5,%6,%7}, {%8,%9}, {%0,%1,%2,%3};"
                 : "+f"(c[0]), "+f"(c[1]), "+f"(c[2]), "+f"(c[3])
                 : "r"(a[0]), "r"(a[1]), "r"(a[2]), "r"(a[3]), "r"(b[0]), "r"(b[1]));
}
__device__ __forceinline__ void cp_async16(uint32_t saddr, const void* gptr) {
    asm volatile("cp.async.cg.shared.global [%0], [%1], 16;" :: "r"(saddr), "l"(gptr));
}
#define CP_COMMIT() asm volatile("cp.async.commit_group;" ::: "memory")
#define CP_WAIT2() asm volatile("cp.async.wait_group 2;" ::: "memory")
#define CP_WAIT1() asm volatile("cp.async.wait_group 1;" ::: "memory")
#define CP_WAIT0() asm volatile("cp.async.wait_group 0;" ::: "memory")

__device__ __forceinline__ uint32_t pack_bf2_hi(float a, float b) {
    __nv_bfloat162 t; t.x = __float2bfloat16(a); t.y = __float2bfloat16(b);
    return *(uint32_t*)&t;
}
__device__ __forceinline__ uint32_t pack_bf2_lo(float a, float b) {
    float ra = a - __bfloat162float(__float2bfloat16(a));
    float rb = b - __bfloat162float(__float2bfloat16(b));
    __nv_bfloat162 t; t.x = __float2bfloat16(ra); t.y = __float2bfloat16(rb);
    return *(uint32_t*)&t;
}

// -------- K0: x (B,C,H,W) -> xt (B,H,W,C), tiled transpose --------
__global__ void k_transpose_x(const float* __restrict__ x) {
    __shared__ float tile[32][33];
    int b = blockIdx.z;
    int c0 = blockIdx.y * 32, p0 = blockIdx.x * 32;
    #pragma unroll
    for (int i = threadIdx.y; i < 32; i += 8)
        tile[i][threadIdx.x] = x[((size_t)(b * NC + c0 + i) << 12) + p0 + threadIdx.x];
    __syncthreads();
    #pragma unroll
    for (int i = threadIdx.y; i < 32; i += 8)
        g_xt[(((size_t)b << 12) + p0 + i) * NC + c0 + threadIdx.x] = tile[threadIdx.x][i];
}

// -------- K1: poly eval + bilinear sample -> Ahi/Alo[b,n,s,c] (bf16 split) --------
__global__ void k_sample(const float* __restrict__ polys) {
    int j = blockIdx.x;                                // 0..58799 = ((b*600+n)*49+s)
    int t = threadIdx.x;                               // 0..63, 4 channels each
    int b = j / (NWIN * WS2);
    int r = j - b * (NWIN * WS2);
    int n = r / WS2;
    int s = r - n * WS2;
    int q = n / NP;
    int nid = n - q * NP;
    int m = nid * WS2 + s;
    int w = m / NP;
    int p = m - w * NP;

    const float* pc = polys + ((size_t)(b * NQ + q) * 2) * NP;
    float a = (float)p * 0.2f;
    float py = pc[0];
    #pragma unroll
    for (int i = 1; i < NP; i++) py = py * a + pc[i];
    float px = pc[NP];
    #pragma unroll
    for (int i = 1; i < NP; i++) px = px * a + pc[NP + i];
    py = 2.f * py - 1.f;
    px = 2.f * px - 1.f;

    int wy = w / WSZ, wx = w - wy * WSZ;
    float dy = (-4.0f + (float)wy * (7.0f / 6.0f)) * (2.0f / 64.0f);
    float dx = (-4.0f + (float)wx * (7.0f / 6.0f)) * (2.0f / 64.0f);
    float gy = py + dy, gx = px + dx;

    float fx = (gy + 1.f) * 0.5f * 63.f;
    float fy = (gx + 1.f) * 0.5f * 63.f;
    float x0f = floorf(fx), y0f = floorf(fy);
    float wx1 = fx - x0f, wy1 = fy - y0f;

    float vx0 = (x0f >= 0.f && x0f <= 63.f) ? 1.f : 0.f;
    float vx1 = (x0f + 1.f >= 0.f && x0f + 1.f <= 63.f) ? 1.f : 0.f;
    float vy0 = (y0f >= 0.f && y0f <= 63.f) ? 1.f : 0.f;
    float vy1 = (y0f + 1.f >= 0.f && y0f + 1.f <= 63.f) ? 1.f : 0.f;
    int xi0 = min(max((int)x0f, 0), 63);
    int xi1 = min(max((int)x0f + 1, 0), 63);
    int yi0 = min(max((int)y0f, 0), 63);
    int yi1 = min(max((int)y0f + 1, 0), 63);

    float w00 = (1.f - wy1) * (1.f - wx1) * vy0 * vx0;
    float w01 = (1.f - wy1) * wx1 * vy0 * vx1;
    float w10 = wy1 * (1.f - wx1) * vy1 * vx0;
    float w11 = wy1 * wx1 * vy1 * vx1;

    const float4* xt4 = (const float4*)g_xt;
    size_t pbase = (size_t)b * 4096;
    const float4* p00 = xt4 + (pbase + yi0 * 64 + xi0) * 64;
    const float4* p01 = xt4 + (pbase + yi0 * 64 + xi1) * 64;
    const float4* p10 = xt4 + (pbase + yi1 * 64 + xi0) * 64;
    const float4* p11 = xt4 + (pbase + yi1 * 64 + xi1) * 64;
    float4 v00 = p00[t], v01 = p01[t], v10 = p10[t], v11 = p11[t];
    float4 o;
    o.x = w00 * v00.x + w01 * v01.x + w10 * v10.x + w11 * v11.x;
    o.y = w00 * v00.y + w01 * v01.y + w10 * v10.y + w11 * v11.y;
    o.z = w00 * v00.z + w01 * v01.z + w10 * v10.z + w11 * v11.z;
    o.w = w00 * v00.w + w01 * v01.w + w10 * v10.w + w11 * v11.w;

    uint2 hv, lv;
    hv.x = pack_bf2_hi(o.x, o.y); hv.y = pack_bf2_hi(o.z, o.w);
    lv.x = pack_bf2_lo(o.x, o.y); lv.y = pack_bf2_lo(o.z, o.w);
    size_t base2 = (size_t)j * 64 + t;                 // uint2 units
    ((uint2*)g_ahi)[base2] = hv;
    ((uint2*)g_alo)[base2] = lv;
}

// -------- K1b: w_qkv -> per-lane MMA B-fragments (hi/lo packed in one uint4) --------
__global__ void k_wfrag(const float* __restrict__ wq) {
    int i = blockIdx.x * 256 + threadIdx.x;            // < 49152
    int lane = i & 31;
    int kt = (i >> 5) & 15;
    int nt = i >> 9;
    int n = nt * 8 + (lane >> 2);
    int kb = kt * 16 + (lane & 3) * 2;
    const float* row = wq + (size_t)n * KD;
    float v00 = row[kb],     v01 = row[kb + 1];
    float v10 = row[kb + 8], v11 = row[kb + 9];
    uint4 bf;
    bf.x = pack_bf2_hi(v00, v01);
    bf.y = pack_bf2_hi(v10, v11);
    bf.z = pack_bf2_lo(v00, v01);
    bf.w = pack_bf2_lo(v10, v11);
    g_bfrag[i] = bf;
}

// -------- K2: HMMA GEMM, CTA tile 128x128, 2 CTAs/SM, 3-stage cp.async --------
// 8 warps 4m x 2n, warp tile 32x64, K chunk 64 (4 iters).
// 3 bf16 terms: Ah*Bh + Ah*Bl + Al*Bh. Dep spacing 4 via j-pair interleave.
#define SROWB 144                   // smem row stride bytes (64 bf16 data + 16B pad)
#define ARR2_B (128 * SROWB)        // 18432 B per array
#define STAGE2_B (2 * ARR2_B)       // 36864 B per stage (A hi + A lo)
#define GSM_TOTAL (3 * STAGE2_B)    // 110592 B (3 stages)

__global__ void __launch_bounds__(256, 2) k_gemm_mma(const float* __restrict__ bq) {
    extern __shared__ __align__(16) char dsm[];
    int tid = threadIdx.x;
    int wid = tid >> 5, lid = tid & 31;
    int wm = wid >> 1, wn = wid & 1;                   // 4 x 2 warp grid
    int bm = blockIdx.x * 128, bn = blockIdx.y * 128;

    float acc[2][8][4];
    #pragma unroll
    for (int t = 0; t < 2; t++)
        #pragma unroll
        for (int j = 0; j < 8; j++)
            #pragma unroll
            for (int e = 0; e < 4; e++) acc[t][j][e] = 0.f;

    uint32_t sbase = smem_u32(dsm);

    const char* GAh = (const char*)g_ahi;
    const char* GAl = (const char*)g_alo;
    const uint4* BF = (const uint4*)g_bfrag;
    int wb = ((bn + wn * 64) >> 3) * 512 + lid;

    int arow = lid & 15;
    int acolb = (lid >> 4) * 16;
    uint32_t aA0 = (uint32_t)((wm * 32 + arow) * SROWB) + acolb;

    auto load_stage = [&](int kc, int st) {
        uint32_t sb = sbase + st * STAGE2_B;
        #pragma unroll
        for (int i = tid; i < 1024; i += 256) {
            int row = i >> 3, u = i & 7;
            uint32_t so = (uint32_t)(row * SROWB) + u * 16;
            size_t ga = (size_t)(bm + row) * 512 + kc * 128 + u * 16;
            cp_async16(sb + so,          GAh + ga);
            cp_async16(sb + ARR2_B + so, GAl + ga);
        }
    };

    load_stage(0, 0);
    CP_COMMIT();
    load_stage(1, 1);
    CP_COMMIT();

    for (int kc = 0; kc < 4; kc++) {
        int st = kc - (kc >= 3 ? 3 : 0);               // kc % 3
        if (kc < 2) {
            load_stage(kc + 2, (kc + 2) % 3);          // stage (kc+2)%3 free since compute kc-1 synced
            CP_COMMIT();
            CP_WAIT2();
        } else if (kc == 2) {
            CP_WAIT1();
        } else {
            CP_WAIT0();
        }
        __syncthreads();

        uint32_t uAh = sbase + st * STAGE2_B;
        uint32_t uAl = uAh + ARR2_B;
        #pragma unroll
        for (int ks = 0; ks < 4; ks++) {
            int ktoff = (kc * 4 + ks) * 32;
            uint32_t ah[2][4], al[2][4];
            ldsm_x4(ah[0], uAh + aA0 + ks * 32);
            ldsm_x4(ah[1], uAh + aA0 + 16 * SROWB + ks * 32);
            ldsm_x4(al[0], uAl + aA0 + ks * 32);
            ldsm_x4(al[1], uAl + aA0 + 16 * SROWB + ks * 32);
            uint4 b0 = BF[wb + 0 * 512 + ktoff];
            uint4 b1 = BF[wb + 1 * 512 + ktoff];
            #pragma unroll
            for (int jp = 0; jp < 4; jp++) {
                uint4 n0, n1;
                if (jp < 3) {
                    n0 = BF[wb + (jp * 2 + 2) * 512 + ktoff];
                    n1 = BF[wb + (jp * 2 + 3) * 512 + ktoff];
                }
                int ja = jp * 2, jb = ja + 1;
                const uint32_t* p0 = (const uint32_t*)&b0;
                const uint32_t* p1 = (const uint32_t*)&b1;
                mma16816(acc[0][ja], ah[0], p0);
                mma16816(acc[0][jb], ah[0], p1);
                mma16816(acc[1][ja], ah[1], p0);
                mma16816(acc[1][jb], ah[1], p1);
                mma16816(acc[0][ja], ah[0], p0 + 2);
                mma16816(acc[0][jb], ah[0], p1 + 2);
                mma16816(acc[1][ja], ah[1], p0 + 2);
                mma16816(acc[1][jb], ah[1], p1 + 2);
                mma16816(acc[0][ja], al[0], p0);
                mma16816(acc[0][jb], al[0], p1);
                mma16816(acc[1][ja], al[1], p0);
                mma16816(acc[1][jb], al[1], p1);
                b0 = n0; b1 = n1;
            }
        }
        __syncthreads();
    }

    // epilogue: c-frag + bias -> interleaved uint2 {hi2, lo2} per col-pair
    int crow0 = bm + wm * 32 + (lid >> 2);
    int ccol0 = bn + wn * 64 + (lid & 3) * 2;
    #pragma unroll
    for (int t = 0; t < 2; t++) {
        #pragma unroll
        for (int j = 0; j < 8; j++) {
            int col = ccol0 + j * 8;
            float b0 = __ldg(&bq[col]);
            float b1 = __ldg(&bq[col + 1]);
            int row = crow0 + t * 16;
            float v00 = acc[t][j][0] + b0, v01 = acc[t][j][1] + b1;
            float v10 = acc[t][j][2] + b0, v11 = acc[t][j][3] + b1;
            uint2 s0, s1;
            s0.x = pack_bf2_hi(v00, v01); s0.y = pack_bf2_lo(v00, v01);
            s1.x = pack_bf2_hi(v10, v11); s1.y = pack_bf2_lo(v10, v11);
            g_qhl[((size_t)row * NOUT3 + col) >> 1] = s0;
            g_qhl[((size_t)(row + 8) * NOUT3 + col) >> 1] = s1;
        }
    }
}

// -------- K3: HMMA windowed attention, one (b,h,n) per block, 128 threads --------
// Pad rows/cols of q/k/P left as garbage: they only propagate to S rows>=49,
// S cols>=52 (masked in softmax) and O rows>=49 (never stored). vT pad cols are
// zero-filled in the fill loop (needed: P=0 x V=NaN would poison O).
#define ATT_QH 0            // 64 x 80B  (later PH: 64 x 144B)
#define ATT_QL 5120
#define ATT_KH 10240        // (later PL)
#define ATT_KL 15360
#define ATT_VTH 20480       // 32 x 144B
#define ATT_VTL 25088
#define ATT_S 29696         // 64 x 68 floats = 17408 (reused as O: 64 x 36 floats)
#define ATT_PH 0
#define ATT_PL 10240
#define ATT_SM 47104
#define SSTR 68

__global__ void __launch_bounds__(128) k_attn_mma(const float* __restrict__ pos_bias) {
    extern __shared__ __align__(16) char sma[];
    int tid = threadIdx.x;
    int wid = tid >> 5, lid = tid & 31;
    int blk = blockIdx.x;
    int b = blk / (NHD * NWIN);
    int r = blk - b * NHD * NWIN;
    int h = r / NWIN;
    int n = r - h * NWIN;
    uint32_t sb = smem_u32(sma);

    // 1. fill q/k (rows<49) and transposed v (cols>=49 zeroed inline)
    const uint4* GQ = (const uint4*)g_qhl;             // 1 uint4 = 4 cols {hi2,lo2}x2
    int grow0 = (b * NWIN + n) * WS2;
    for (int idx = tid; idx < 392; idx += 128) {       // q+k: 49 rows x 8 colgroups
        int row = idx >> 3, cg = idx & 7;
        size_t base = (size_t)(grow0 + row) * 192 + h * 8 + cg;
        uint4 vq = GQ[base];
        uint4 vk = GQ[base + 64];
        uint2 qh; qh.x = vq.x; qh.y = vq.z;
        uint2 ql; ql.x = vq.y; ql.y = vq.w;
        uint2 kh; kh.x = vk.x; kh.y = vk.z;
        uint2 kl; kl.x = vk.y; kl.y = vk.w;
        *(uint2*)(sma + ATT_QH + row * 80 + cg * 8) = qh;
        *(uint2*)(sma + ATT_QL + row * 80 + cg * 8) = ql;
        *(uint2*)(sma + ATT_KH + row * 80 + cg * 8) = kh;
        *(uint2*)(sma + ATT_KL + row * 80 + cg * 8) = kl;
    }
    for (int idx = tid; idx < 1024; idx += 128) {      // vT: [d=32][c=64]
        int c = idx >> 4, u = idx & 15;                // u = d-pair
        uint2 w = make_uint2(0u, 0u);
        if (c < WS2)
            w = ((const uint2*)g_qhl)[(size_t)(grow0 + c) * 384 + 256 + h * 16 + u];
        __nv_bfloat162 vh2 = *(__nv_bfloat162*)&w.x;
        __nv_bfloat162 vl2 = *(__nv_bfloat162*)&w.y;
        __nv_bfloat16* th = (__nv_bfloat16*)(sma + ATT_VTH);
        __nv_bfloat16* tl = (__nv_bfloat16*)(sma + ATT_VTL);
        th[(2 * u) * 72 + c] = vh2.x; th[(2 * u + 1) * 72 + c] = vh2.y;
        tl[(2 * u) * 72 + c] = vl2.x; tl[(2 * u + 1) * 72 + c] = vl2.y;
    }
    __syncthreads();

    // 2. S = q k^T via HMMA (3-term hi/lo)
    {
        float accs[8][4];
        #pragma unroll
        for (int j = 0; j < 8; j++)
            #pragma unroll
            for (int e = 0; e < 4; e++) accs[j][e] = 0.f;
        int arow = lid & 15, acolb = (lid >> 4) * 16;
        int brow = ((lid >> 4) & 1) * 8 + (lid & 7);
        int bcolb = ((lid >> 3) & 1) * 16;
        uint32_t aQh = sb + ATT_QH + (wid * 16 + arow) * 80 + acolb;
        uint32_t aQl = sb + ATT_QL + (wid * 16 + arow) * 80 + acolb;
        uint32_t aKh = sb + ATT_KH + brow * 80 + bcolb;
        uint32_t aKl = sb + ATT_KL + brow * 80 + bcolb;
        #pragma unroll
        for (int ks = 0; ks < 2; ks++) {
            uint32_t ah[4], al[4];
            ldsm_x4(ah, aQh + ks * 32);
            ldsm_x4(al, aQl + ks * 32);
            #pragma unroll
            for (int g = 0; g < 4; g++) {
                uint32_t bh[4], bl[4];
                ldsm_x4(bh, aKh + g * 16 * 80 + ks * 32);
                ldsm_x4(bl, aKl + g * 16 * 80 + ks * 32);
                mma16816(accs[g * 2],     ah, bh);
                mma16816(accs[g * 2 + 1], ah, bh + 2);
                mma16816(accs[g * 2],     ah, bl);
                mma16816(accs[g * 2 + 1], ah, bl + 2);
                mma16816(accs[g * 2],     al, bh);
                mma16816(accs[g * 2 + 1], al, bh + 2);
            }
        }
        float* S = (float*)(sma + ATT_S);
        int srow = wid * 16 + (lid >> 2), scol = (lid & 3) * 2;
        #pragma unroll
        for (int j = 0; j < 8; j++) {
            *(float2*)&S[srow * SSTR + j * 8 + scol]       = make_float2(accs[j][0], accs[j][1]);
            *(float2*)&S[(srow + 8) * SSTR + j * 8 + scol] = make_float2(accs[j][2], accs[j][3]);
        }
    }
    __syncthreads();

    // 3. vectorized fp32 softmax per row (<49); write full 144B P rows (tails = 0)
    if (tid < WS2) {
        const float scale = 0.17677669529663687f;
        float pb = pos_bias[tid];
        const float4* S4 = (const float4*)(sma + ATT_S) + tid * (SSTR / 4);
        float4 rv[13];
        #pragma unroll
        for (int i = 0; i < 13; i++) rv[i] = S4[i];
        #pragma unroll
        for (int i = 0; i < 13; i++) {
            rv[i].x = rv[i].x * scale + pb; rv[i].y = rv[i].y * scale + pb;
            rv[i].z = rv[i].z * scale + pb; rv[i].w = rv[i].w * scale + pb;
        }
        float mx = rv[12].x;
        #pragma unroll
        for (int i = 0; i < 12; i++)
            mx = fmaxf(mx, fmaxf(fmaxf(rv[i].x, rv[i].y), fmaxf(rv[i].z, rv[i].w)));
        float sum = 0.f;
        #pragma unroll
        for (int i = 0; i < 12; i++) {
            rv[i].x = __expf(rv[i].x - mx); rv[i].y = __expf(rv[i].y - mx);
            rv[i].z = __expf(rv[i].z - mx); rv[i].w = __expf(rv[i].w - mx);
            sum += rv[i].x + rv[i].y + rv[i].z + rv[i].w;
        }
        rv[12].x = __expf(rv[12].x - mx);
        rv[12].y = 0.f; rv[12].z = 0.f; rv[12].w = 0.f;
        sum += rv[12].x;
        float inv = 1.f / sum;
        uint32_t* PH32 = (uint32_t*)(sma + ATT_PH) + tid * 36;
        uint32_t* PL32 = (uint32_t*)(sma + ATT_PL) + tid * 36;
        #pragma unroll
        for (int cp = 0; cp < 26; cp++) {
            float a  = ((cp & 1) ? rv[cp >> 1].z : rv[cp >> 1].x) * inv;
            float b2 = ((cp & 1) ? rv[cp >> 1].w : rv[cp >> 1].y) * inv;
            PH32[cp] = pack_bf2_hi(a, b2);
            PL32[cp] = pack_bf2_lo(a, b2);
        }
        #pragma unroll
        for (int cp = 26; cp < 36; cp++) { PH32[cp] = 0u; PL32[cp] = 0u; }
    }
    __syncthreads();

    // 4. O = P V via HMMA (3-term)
    {
        float acco[4][4];
        #pragma unroll
        for (int j = 0; j < 4; j++)
            #pragma unroll
            for (int e = 0; e < 4; e++) acco[j][e] = 0.f;
        int arow = lid & 15, acolb = (lid >> 4) * 16;
        int brow = ((lid >> 4) & 1) * 8 + (lid & 7);
        int bcolb = ((lid >> 3) & 1) * 16;
        uint32_t aPh = sb + ATT_PH + (wid * 16 + arow) * 144 + acolb;
        uint32_t aPl = sb + ATT_PL + (wid * 16 + arow) * 144 + acolb;
        uint32_t aVh = sb + ATT_VTH + brow * 144 + bcolb;
        uint32_t aVl = sb + ATT_VTL + brow * 144 + bcolb;
        #pragma unroll
        for (int ks = 0; ks < 4; ks++) {
            uint32_t ph[4], pl[4];
            ldsm_x4(ph, aPh + ks * 32);
            ldsm_x4(pl, aPl + ks * 32);
            #pragma unroll
            for (int g = 0; g < 2; g++) {
                uint32_t vh[4], vl[4];
                ldsm_x4(vh, aVh + g * 16 * 144 + ks * 32);
                ldsm_x4(vl, aVl + g * 16 * 144 + ks * 32);
                mma16816(acco[g * 2],     ph, vh);
                mma16816(acco[g * 2 + 1], ph, vh + 2);
                mma16816(acco[g * 2],     ph, vl);
                mma16816(acco[g * 2 + 1], ph, vl + 2);
                mma16816(acco[g * 2],     pl, vh);
                mma16816(acco[g * 2 + 1], pl, vh + 2);
            }
        }
        float* O = (float*)(sma + ATT_S);
        int orow = wid * 16 + (lid >> 2), ocol = (lid & 3) * 2;
        #pragma unroll
        for (int j = 0; j < 4; j++) {
            *(float2*)&O[orow * 36 + j * 8 + ocol]       = make_float2(acco[j][0], acco[j][1]);
            *(float2*)&O[(orow + 8) * 36 + j * 8 + ocol] = make_float2(acco[j][2], acco[j][3]);
        }
    }
    __syncthreads();

    // 5. store o[p<49][d<32] to scrambled-flat g_o
    size_t obase = (size_t)b * OB_PER_B + (size_t)h * (WS2 * NWIN * HDD) + (size_t)n * HDD;
    const float* O = (const float*)(sma + ATT_S);
    for (int idx = tid; idx < WS2 * 8; idx += 128) {
        int p = idx >> 3, d4 = (idx & 7) * 4;
        float4 v = *(const float4*)&O[p * 36 + d4];
        *(float4*)&g_o[obase + (size_t)p * (NWIN * HDD) + d4] = v;
    }
}

// -------- K4: conv reduce over scrambled s2 axis (float4) --------
__global__ void k_conv(const float* __restrict__ conv_w, const float* __restrict__ conv_b) {
    __shared__ float cw[WS2];
    int tid = threadIdx.x;
    if (tid < WS2) cw[tid] = conv_w[tid];
    __syncthreads();
    int idx = blockIdx.x * 256 + tid;                  // < 76800 (c4 granularity)
    int b = idx / (NWIN * 64);
    int r = idx - b * (NWIN * 64);
    int n2 = r >> 6, c4 = r & 63;
    size_t base = (size_t)b * OB_PER_B + (size_t)n2 * (WS2 * NC) + c4 * 4;
    float cb = conv_b[0];
    float4 acc = make_float4(cb, cb, cb, cb);
    #pragma unroll 7
    for (int s2 = 0; s2 < WS2; s2++) {
        float4 v = *(const float4*)&g_o[base + (size_t)s2 * NC];
        float w = cw[s2];
        acc.x += w * v.x; acc.y += w * v.y; acc.z += w * v.z; acc.w += w * v.w;
    }
    *(float4*)&g_ypre[(size_t)idx * 4] = acc;
}

// -------- K5a: transpose w_proj --------
__global__ void k_wpt(const float* __restrict__ wp) {
    int idx = blockIdx.x * 256 + threadIdx.x;          // < 65536
    int k = idx >> 8, c = idx & 255;
    g_wpT[idx] = wp[c * NC + k];
}

// -------- K5b: y = ypre @ w_proj^T + b_proj (8 rows/block) --------
#define PR 8
__global__ void __launch_bounds__(256) k_proj(const float* __restrict__ bp, float* __restrict__ out) {
    __shared__ float rowv[PR][NC];
    int row0 = blockIdx.x * PR;
    int tid = threadIdx.x;
    for (int i = tid; i < PR * NC; i += 256)
        rowv[i >> 8][i & 255] = g_ypre[(size_t)(row0 + (i >> 8)) * NC + (i & 255)];
    __syncthreads();
    int c = tid;
    float acc[PR];
    #pragma unroll
    for (int i = 0; i < PR; i++) acc[i] = 0.f;
    #pragma unroll 4
    for (int k = 0; k < NC; k++) {
        float wv = g_wpT[k * NC + c];
        #pragma unroll
        for (int i = 0; i < PR; i++) acc[i] += rowv[i][k] * wv;
    }
    float bb = bp[c];
    #pragma unroll
    for (int i = 0; i < PR; i++)
        out[(size_t)(row0 + i) * NC + c] = acc[i] + bb;
}

extern "C" void kernel_launch(void* const* d_in, const int* in_sizes, int n_in,
                              void* d_out, int out_size) {
    const float* x        = (const float*)d_in[0];
    const float* polys    = (const float*)d_in[1];
    const float* w_qkv    = (const float*)d_in[2];
    const float* b_qkv    = (const float*)d_in[3];
    const float* w_proj   = (const float*)d_in[4];
    const float* b_proj   = (const float*)d_in[5];
    const float* conv_w   = (const float*)d_in[6];
    const float* conv_b   = (const float*)d_in[7];
    const float* pos_bias = (const float*)d_in[8];
    float* out = (float*)d_out;

    static int smem_set = 0;
    if (!smem_set) {
        cudaFuncSetAttribute(k_gemm_mma, cudaFuncAttributeMaxDynamicSharedMemorySize, GSM_TOTAL);
        cudaFuncSetAttribute(k_attn_mma, cudaFuncAttributeMaxDynamicSharedMemorySize, ATT_SM);
        smem_set = 1;
    }

    dim3 gt(128, 8, 2);
    dim3 bt(32, 8);
    k_transpose_x<<<gt, bt>>>(x);
    k_sample<<<NROWS, 64>>>(polys);
    k_wfrag<<<(96 * 16 * 32) / 256, 256>>>(w_qkv);
    dim3 g2(MPAD / 128, NOUT3 / 128);
    k_gemm_mma<<<g2, 256, GSM_TOTAL>>>(b_qkv);
    k_attn_mma<<<NB * NHD * NWIN, 128, ATT_SM>>>(pos_bias);
    k_conv<<<(NB * NWIN * 64) / 256, 256>>>(conv_w, conv_b);
    k_wpt<<<NC * NC / 256, 256>>>(w_proj);
    k_proj<<<NB * NWIN / PR, 256>>>(b_proj, out);
}